// round 6
// baseline (speedup 1.0000x reference)
#include <cuda_runtime.h>
#include <cuda_fp16.h>
#include <cstdint>

#define CCH 768
#define NK  192
#define NCHUNK 12
#define NT 512

// smem (bytes):
//  projection: XH fp16 [128][72] @0 (18432); W bufs @18432, per buf 51200 (hi 25600, lo 25600)
//              -> end 120832
//  attention overlay: KS/QS/VS/PS fp32, each 2*64*65*4 = 33280 -> 133120 total
#define WOFF(b) (18432 + (b) * 51200)
#define SMEM_BYTES 133120

__device__ __align__(16) __half g_Whi[CCH * NK];
__device__ __align__(16) __half g_Wlo[CCH * NK];

__global__ void prep_weights(const float* __restrict__ Wk,
                             const float* __restrict__ Wq,
                             const float* __restrict__ Wv) {
    int i = blockIdx.x * blockDim.x + threadIdx.x;
    if (i >= CCH * NK) return;
    int c = i / NK, n = i % NK;
    const float* W = (n < 64) ? Wk : (n < 128) ? Wq : Wv;
    float w = W[c * 64 + (n & 63)];
    __half h = __float2half_rn(w);
    g_Whi[i] = h;
    g_Wlo[i] = __float2half_rn(w - __half2float(h));
}

__device__ __forceinline__ uint32_t sptr(const void* p) {
    return (uint32_t)__cvta_generic_to_shared(p);
}
__device__ __forceinline__ void ldsm_x4(uint32_t* r, uint32_t addr) {
    asm volatile("ldmatrix.sync.aligned.m8n8.x4.shared.b16 {%0,%1,%2,%3}, [%4];"
                 : "=r"(r[0]), "=r"(r[1]), "=r"(r[2]), "=r"(r[3]) : "r"(addr));
}
__device__ __forceinline__ void ldsm_x4t(uint32_t* r, uint32_t addr) {
    asm volatile("ldmatrix.sync.aligned.m8n8.x4.trans.shared.b16 {%0,%1,%2,%3}, [%4];"
                 : "=r"(r[0]), "=r"(r[1]), "=r"(r[2]), "=r"(r[3]) : "r"(addr));
}
__device__ __forceinline__ void mma16816(float* c, const uint32_t* a, const uint32_t* b) {
    asm volatile("mma.sync.aligned.m16n8k16.row.col.f32.f16.f16.f32 "
                 "{%0,%1,%2,%3}, {%4,%5,%6,%7}, {%8,%9}, {%0,%1,%2,%3};"
                 : "+f"(c[0]), "+f"(c[1]), "+f"(c[2]), "+f"(c[3])
                 : "r"(a[0]), "r"(a[1]), "r"(a[2]), "r"(a[3]), "r"(b[0]), "r"(b[1]));
}
__device__ __forceinline__ void cpasync16(uint32_t d, const void* s) {
    asm volatile("cp.async.cg.shared.global [%0], [%1], 16;" :: "r"(d), "l"(s));
}

extern "C" __global__ void __launch_bounds__(NT, 1)
head_main(const float* __restrict__ x, float* __restrict__ out) {
    extern __shared__ char smem[];
    __half* XH = (__half*)smem;

    const int tid = threadIdx.x;
    const int w = tid >> 5;
    const int lane = tid & 31;

    const float* xb = x + (size_t)blockIdx.x * 128 * CCH;

    // -------- prefetch x chunk 0: 128 rows x 16 float4; 4 float4/thread
    float4 xr[4];
#pragma unroll
    for (int i = 0; i < 4; i++) {
        int idx = i * NT + tid;
        xr[i] = *(const float4*)(xb + (idx >> 4) * CCH + (idx & 15) * 4);
    }

    // -------- issue W chunk 0 -> buf 0
#pragma unroll
    for (int j = 0; j < 3; j++) {
        int idx = j * NT + tid;                 // 1536: 64 k-rows x 24 16B-segs
        int row = idx / 24, c16 = (idx % 24) * 8;
        uint32_t dh = sptr(smem + WOFF(0)) + (uint32_t)(row * 400 + c16 * 2);
        cpasync16(dh, g_Whi + row * NK + c16);
        cpasync16(dh + 25600, g_Wlo + row * NK + c16);
    }
    asm volatile("cp.async.commit_group;" ::: "memory");

    // warp grid 4x4: M32 x N48 per warp
    const int mwarp = w & 3;                    // M tile of 32 rows
    const int nwarp = w >> 2;                   // N tile of 48 cols

    float acc[12][4];                           // [mt*6 + jn][4], mt<2, jn<6
#pragma unroll
    for (int jt = 0; jt < 12; jt++)
#pragma unroll
        for (int r = 0; r < 4; r++) acc[jt][r] = 0.0f;

    const int a_base = (mwarp * 32 + (lane & 15)) * 72 + (lane >> 4) * 8;  // halves
    const int b_base = nwarp * 48 + (lane >> 4) * 8;                       // col part
    const int b_row = lane & 15;

#pragma unroll 1
    for (int kc = 0; kc < NCHUNK; kc++) {
        const int buf = kc & 1;
        __syncthreads();  // prev chunk's MMA reads of XH and W[buf^1] complete

        if (kc + 1 < NCHUNK) {
            const size_t gk = (size_t)(kc + 1) * 64 * NK;
#pragma unroll
            for (int j = 0; j < 3; j++) {
                int idx = j * NT + tid;
                int row = idx / 24, c16 = (idx % 24) * 8;
                uint32_t dh = sptr(smem + WOFF(buf ^ 1)) + (uint32_t)(row * 400 + c16 * 2);
                cpasync16(dh, g_Whi + gk + row * NK + c16);
                cpasync16(dh + 25600, g_Wlo + gk + row * NK + c16);
            }
            asm volatile("cp.async.commit_group;" ::: "memory");
        }

        // x regs -> XH fp16 (single rounding)
#pragma unroll
        for (int i = 0; i < 4; i++) {
            int idx = i * NT + tid;
            int r = idx >> 4, s = idx & 15;
            float4 v = xr[i];
            __half2 h01 = __floats2half2_rn(v.x, v.y);
            __half2 h23 = __floats2half2_rn(v.z, v.w);
            uint2 pkt;
            pkt.x = *(uint32_t*)&h01;
            pkt.y = *(uint32_t*)&h23;
            *(uint2*)((char*)XH + (uint32_t)(r * 144 + s * 8)) = pkt;
        }

        if (kc + 1 < NCHUNK) asm volatile("cp.async.wait_group 1;" ::: "memory");
        else                 asm volatile("cp.async.wait_group 0;" ::: "memory");
        __syncthreads();  // XH + W[buf] visible to all

        const __half* WHs = (const __half*)(smem + WOFF(buf));
        const __half* WLs = WHs + 12800;

#pragma unroll
        for (int ks = 0; ks < 4; ks++) {
            uint32_t ah0[4], ah1[4];
            ldsm_x4(ah0, sptr(XH + a_base + ks * 16));
            ldsm_x4(ah1, sptr(XH + a_base + 16 * 72 + ks * 16));
            const int br = (ks * 16 + b_row) * 200 + b_base;
            uint32_t bh[12], bl[12];
#pragma unroll
            for (int j = 0; j < 3; j++) {
                ldsm_x4t(bh + 4 * j, sptr(WHs + br + j * 16));
                ldsm_x4t(bl + 4 * j, sptr(WLs + br + j * 16));
            }

            // prefetch next x chunk mid-MMA (xr live range starts here, after B temps peak)
            if (ks == 2 && kc + 1 < NCHUNK) {
#pragma unroll
                for (int i = 0; i < 4; i++) {
                    int idx = i * NT + tid;
                    xr[i] = *(const float4*)(xb + (idx >> 4) * CCH + (kc + 1) * 64 + (idx & 15) * 4);
                }
            }

            // hi pass: 12 MMAs, 12 distinct accumulators (no RAW)
#pragma unroll
            for (int j = 0; j < 3; j++) {
                mma16816(acc[0 * 6 + 2 * j],     ah0, bh + 4 * j);
                mma16816(acc[0 * 6 + 2 * j + 1], ah0, bh + 4 * j + 2);
                mma16816(acc[1 * 6 + 2 * j],     ah1, bh + 4 * j);
                mma16816(acc[1 * 6 + 2 * j + 1], ah1, bh + 4 * j + 2);
            }
            // lo pass: accumulator reuse distance = 12 MMAs
#pragma unroll
            for (int j = 0; j < 3; j++) {
                mma16816(acc[0 * 6 + 2 * j],     ah0, bl + 4 * j);
                mma16816(acc[0 * 6 + 2 * j + 1], ah0, bl + 4 * j + 2);
                mma16816(acc[1 * 6 + 2 * j],     ah1, bl + 4 * j);
                mma16816(acc[1 * 6 + 2 * j + 1], ah1, bl + 4 * j + 2);
            }
        }
    }
    __syncthreads();  // projection done; smem repurposed

    // -------- fragments -> KS/QS/VS (fp32, row pad 65)
    float* KS = (float*)smem;
    float* QS = KS + 8320;
    float* VS = QS + 8320;
    float* PS = VS + 8320;
    {
        const int c2 = (lane & 3) * 2;
#pragma unroll
        for (int mt = 0; mt < 2; mt++) {
            const int t0 = mwarp * 32 + mt * 16 + (lane >> 2);
            const int bbx = t0 >> 6, tr = t0 & 63;
#pragma unroll
            for (int jn = 0; jn < 6; jn++) {
                int col = nwarp * 48 + jn * 8 + c2;
                float* dst = (col < 64) ? (KS + col) : (col < 128) ? (QS + col - 64) : (VS + col - 128);
                float* p0 = dst + bbx * 4160 + tr * 65;
                const float* a = acc[mt * 6 + jn];
                p0[0] = a[0];
                p0[1] = a[1];
                p0[8 * 65] = a[2];
                p0[8 * 65 + 1] = a[3];
            }
        }
    }
    __syncthreads();

    // -------- S = q k^T * 0.125, causal softmax (fp32, 2x8 microtile per lane)
    const int bb = w >> 3;             // batch (8 warps each)
    const int i0 = (w & 7) * 8;        // 8 token rows per warp
    const int li = lane >> 3, lj = lane & 7;
    const float* qrow = QS + bb * 4160;
    const float* krow = KS + bb * 4160;

    float s[2][8];
#pragma unroll
    for (int t = 0; t < 2; t++)
#pragma unroll
        for (int m = 0; m < 8; m++) s[t][m] = 0.0f;

#pragma unroll 4
    for (int c = 0; c < 64; c++) {
        float qv[2], kv[8];
#pragma unroll
        for (int t = 0; t < 2; t++) qv[t] = qrow[(i0 + li + 4 * t) * 65 + c];
#pragma unroll
        for (int m = 0; m < 8; m++) kv[m] = krow[(lj + 8 * m) * 65 + c];
#pragma unroll
        for (int t = 0; t < 2; t++)
#pragma unroll
            for (int m = 0; m < 8; m++) s[t][m] += qv[t] * kv[m];
    }

#pragma unroll
    for (int t = 0; t < 2; t++) {
        const int row = i0 + li + 4 * t;
        float mt = -3.0e38f;
#pragma unroll
        for (int m = 0; m < 8; m++) {
            int col = lj + 8 * m;
            float v = s[t][m] * 0.125f;
            v = (col <= row) ? v : -3.0e38f;
            s[t][m] = v;
            mt = fmaxf(mt, v);
        }
        mt = fmaxf(mt, __shfl_xor_sync(0xffffffffu, mt, 1));
        mt = fmaxf(mt, __shfl_xor_sync(0xffffffffu, mt, 2));
        mt = fmaxf(mt, __shfl_xor_sync(0xffffffffu, mt, 4));
        float sum = 0.0f;
#pragma unroll
        for (int m = 0; m < 8; m++) {
            float e = __expf(s[t][m] - mt);
            s[t][m] = e;
            sum += e;
        }
        sum += __shfl_xor_sync(0xffffffffu, sum, 1);
        sum += __shfl_xor_sync(0xffffffffu, sum, 2);
        sum += __shfl_xor_sync(0xffffffffu, sum, 4);
        float inv = 1.0f / sum;
#pragma unroll
        for (int m = 0; m < 8; m++)
            PS[bb * 4160 + row * 65 + lj + 8 * m] = s[t][m] * inv;
    }
    __syncthreads();

    // -------- out = P @ v
    float o[2][8];
#pragma unroll
    for (int t = 0; t < 2; t++)
#pragma unroll
        for (int m = 0; m < 8; m++) o[t][m] = 0.0f;

    const float* prow = PS + bb * 4160;
    const float* vrow = VS + bb * 4160;
#pragma unroll 4
    for (int cs = 0; cs < 64; cs++) {
        float pv[2], vv[8];
#pragma unroll
        for (int t = 0; t < 2; t++) pv[t] = prow[(i0 + li + 4 * t) * 65 + cs];
#pragma unroll
        for (int m = 0; m < 8; m++) vv[m] = vrow[cs * 65 + lj + 8 * m];
#pragma unroll
        for (int t = 0; t < 2; t++)
#pragma unroll
            for (int m = 0; m < 8; m++) o[t][m] += pv[t] * vv[m];
    }
    __syncthreads();  // PS reads done -> reuse as staging

    float* OS = PS;  // [2][64][64]
#pragma unroll
    for (int t = 0; t < 2; t++)
#pragma unroll
        for (int m = 0; m < 8; m++)
            OS[bb * 4096 + (i0 + li + 4 * t) * 64 + lj + 8 * m] = o[t][m];
    __syncthreads();

    float4* og = (float4*)(out + (size_t)blockIdx.x * 8192);
    const float4* os4 = (const float4*)OS;
#pragma unroll
    for (int i = tid; i < 2048; i += NT) og[i] = os4[i];
}

extern "C" void kernel_launch(void* const* d_in, const int* in_sizes, int n_in,
                              void* d_out, int out_size) {
    const float* x  = (const float*)d_in[0];
    const float* Wk = (const float*)d_in[1];
    const float* Wq = (const float*)d_in[2];
    const float* Wv = (const float*)d_in[3];
    float* out = (float*)d_out;

    cudaFuncSetAttribute(head_main, cudaFuncAttributeMaxDynamicSharedMemorySize, SMEM_BYTES);

    prep_weights<<<(CCH * NK + 255) / 256, 256>>>(Wk, Wq, Wv);
    head_main<<<1024, NT, SMEM_BYTES>>>(x, out);
}

// round 7
// speedup vs baseline: 1.1137x; 1.1137x over previous
#include <cuda_runtime.h>
#include <cuda_fp16.h>
#include <cstdint>

#define CCH 768
#define NK  192
#define NCHUNK 12
#define NT 256

// smem (bytes), per CTA (target: 2 CTAs/SM):
//  projection: XH fp16 [64][72] @0 (9216); W bufs @9216, per buf 51200 (hi 25600, lo 25600)
//              -> end 111616
//  attention overlay: KS/QS/VS/PS fp32, each 64*65*4 = 16640 -> 66560 total
#define WOFF(b) (9216 + (b) * 51200)
#define SMEM_BYTES 111616

__device__ __align__(16) __half g_Whi[CCH * NK];
__device__ __align__(16) __half g_Wlo[CCH * NK];

__global__ void prep_weights(const float* __restrict__ Wk,
                             const float* __restrict__ Wq,
                             const float* __restrict__ Wv) {
    int i = blockIdx.x * blockDim.x + threadIdx.x;
    if (i >= CCH * NK) return;
    int c = i / NK, n = i % NK;
    const float* W = (n < 64) ? Wk : (n < 128) ? Wq : Wv;
    float w = W[c * 64 + (n & 63)];
    __half h = __float2half_rn(w);
    g_Whi[i] = h;
    g_Wlo[i] = __float2half_rn(w - __half2float(h));
}

__device__ __forceinline__ uint32_t sptr(const void* p) {
    return (uint32_t)__cvta_generic_to_shared(p);
}
__device__ __forceinline__ void ldsm_x4(uint32_t* r, uint32_t addr) {
    asm volatile("ldmatrix.sync.aligned.m8n8.x4.shared.b16 {%0,%1,%2,%3}, [%4];"
                 : "=r"(r[0]), "=r"(r[1]), "=r"(r[2]), "=r"(r[3]) : "r"(addr));
}
__device__ __forceinline__ void ldsm_x4t(uint32_t* r, uint32_t addr) {
    asm volatile("ldmatrix.sync.aligned.m8n8.x4.trans.shared.b16 {%0,%1,%2,%3}, [%4];"
                 : "=r"(r[0]), "=r"(r[1]), "=r"(r[2]), "=r"(r[3]) : "r"(addr));
}
__device__ __forceinline__ void mma16816(float* c, const uint32_t* a, const uint32_t* b) {
    asm volatile("mma.sync.aligned.m16n8k16.row.col.f32.f16.f16.f32 "
                 "{%0,%1,%2,%3}, {%4,%5,%6,%7}, {%8,%9}, {%0,%1,%2,%3};"
                 : "+f"(c[0]), "+f"(c[1]), "+f"(c[2]), "+f"(c[3])
                 : "r"(a[0]), "r"(a[1]), "r"(a[2]), "r"(a[3]), "r"(b[0]), "r"(b[1]));
}
__device__ __forceinline__ void cpasync16(uint32_t d, const void* s) {
    asm volatile("cp.async.cg.shared.global [%0], [%1], 16;" :: "r"(d), "l"(s));
}

extern "C" __global__ void __launch_bounds__(NT, 2)
head_main(const float* __restrict__ x, float* __restrict__ out) {
    extern __shared__ char smem[];
    __half* XH = (__half*)smem;

    const int tid = threadIdx.x;
    const int w = tid >> 5;
    const int lane = tid & 31;

    const float* xb = x + (size_t)blockIdx.x * 64 * CCH;

    // -------- prefetch x chunk 0: 64 rows x 16 float4; 4 float4/thread
    float4 xr[4];
#pragma unroll
    for (int i = 0; i < 4; i++) {
        int idx = i * NT + tid;
        xr[i] = *(const float4*)(xb + (idx >> 4) * CCH + (idx & 15) * 4);
    }

    // -------- issue W chunk 0 -> buf 0
#pragma unroll
    for (int j = 0; j < 6; j++) {
        int idx = j * NT + tid;                 // 1536: 64 k-rows x 24 16B-segs
        int row = idx / 24, c16 = (idx % 24) * 8;
        uint32_t dh = sptr(smem + WOFF(0)) + (uint32_t)(row * 400 + c16 * 2);
        cpasync16(dh, g_Whi + row * NK + c16);
        cpasync16(dh + 25600, g_Wlo + row * NK + c16);
    }
    asm volatile("cp.async.commit_group;" ::: "memory");

    // warp grid 2x4: M32 x N48 per warp
    const int mwarp = w & 1;                    // M tile of 32 rows
    const int nwarp = w >> 1;                   // N tile of 48 cols

    float acc[12][4];                           // [mt*6 + jn][4], mt<2, jn<6
#pragma unroll
    for (int jt = 0; jt < 12; jt++)
#pragma unroll
        for (int r = 0; r < 4; r++) acc[jt][r] = 0.0f;

    const int a_base = (mwarp * 32 + (lane & 15)) * 72 + (lane >> 4) * 8;  // halves
    const int b_base = nwarp * 48 + (lane >> 4) * 8;                       // col part
    const int b_row = lane & 15;

#pragma unroll 1
    for (int kc = 0; kc < NCHUNK; kc++) {
        const int buf = kc & 1;
        __syncthreads();  // prev chunk's MMA reads of XH and W[buf^1] complete

        if (kc + 1 < NCHUNK) {
            const size_t gk = (size_t)(kc + 1) * 64 * NK;
#pragma unroll
            for (int j = 0; j < 6; j++) {
                int idx = j * NT + tid;
                int row = idx / 24, c16 = (idx % 24) * 8;
                uint32_t dh = sptr(smem + WOFF(buf ^ 1)) + (uint32_t)(row * 400 + c16 * 2);
                cpasync16(dh, g_Whi + gk + row * NK + c16);
                cpasync16(dh + 25600, g_Wlo + gk + row * NK + c16);
            }
            asm volatile("cp.async.commit_group;" ::: "memory");
        }

        // x regs -> XH fp16 (single rounding)
#pragma unroll
        for (int i = 0; i < 4; i++) {
            int idx = i * NT + tid;
            int r = idx >> 4, s = idx & 15;
            float4 v = xr[i];
            __half2 h01 = __floats2half2_rn(v.x, v.y);
            __half2 h23 = __floats2half2_rn(v.z, v.w);
            uint2 pkt;
            pkt.x = *(uint32_t*)&h01;
            pkt.y = *(uint32_t*)&h23;
            *(uint2*)((char*)XH + (uint32_t)(r * 144 + s * 8)) = pkt;
        }

        if (kc + 1 < NCHUNK) asm volatile("cp.async.wait_group 1;" ::: "memory");
        else                 asm volatile("cp.async.wait_group 0;" ::: "memory");
        __syncthreads();  // XH + W[buf] visible to all

        // prefetch next x chunk
        if (kc + 1 < NCHUNK) {
#pragma unroll
            for (int i = 0; i < 4; i++) {
                int idx = i * NT + tid;
                xr[i] = *(const float4*)(xb + (idx >> 4) * CCH + (kc + 1) * 64 + (idx & 15) * 4);
            }
        }

        const __half* WHs = (const __half*)(smem + WOFF(buf));
        const __half* WLs = WHs + 12800;

#pragma unroll
        for (int ks = 0; ks < 4; ks++) {
            uint32_t ah0[4], ah1[4];
            ldsm_x4(ah0, sptr(XH + a_base + ks * 16));
            ldsm_x4(ah1, sptr(XH + a_base + 16 * 72 + ks * 16));
            const int br = (ks * 16 + b_row) * 200 + b_base;
#pragma unroll
            for (int j = 0; j < 3; j++) {
                uint32_t bh[4], bl[4];
                ldsm_x4t(bh, sptr(WHs + br + j * 16));
                ldsm_x4t(bl, sptr(WLs + br + j * 16));
                mma16816(acc[0 * 6 + 2 * j],     ah0, bh);
                mma16816(acc[0 * 6 + 2 * j + 1], ah0, bh + 2);
                mma16816(acc[1 * 6 + 2 * j],     ah1, bh);
                mma16816(acc[1 * 6 + 2 * j + 1], ah1, bh + 2);
                mma16816(acc[0 * 6 + 2 * j],     ah0, bl);
                mma16816(acc[0 * 6 + 2 * j + 1], ah0, bl + 2);
                mma16816(acc[1 * 6 + 2 * j],     ah1, bl);
                mma16816(acc[1 * 6 + 2 * j + 1], ah1, bl + 2);
            }
        }
    }
    __syncthreads();  // projection done; smem repurposed

    // -------- fragments -> KS/QS/VS (fp32, row pad 65)
    float* KS = (float*)smem;
    float* QS = KS + 4160;   // 64*65
    float* VS = QS + 4160;
    float* PS = VS + 4160;
    {
        const int c2 = (lane & 3) * 2;
#pragma unroll
        for (int mt = 0; mt < 2; mt++) {
            const int tr = mwarp * 32 + mt * 16 + (lane >> 2);
#pragma unroll
            for (int jn = 0; jn < 6; jn++) {
                int col = nwarp * 48 + jn * 8 + c2;
                float* dst = (col < 64) ? (KS + col) : (col < 128) ? (QS + col - 64) : (VS + col - 128);
                float* p0 = dst + tr * 65;
                const float* a = acc[mt * 6 + jn];
                p0[0] = a[0];
                p0[1] = a[1];
                p0[8 * 65] = a[2];
                p0[8 * 65 + 1] = a[3];
            }
        }
    }
    __syncthreads();

    // -------- S = q k^T * 0.125, causal softmax (fp32, 2x8 microtile per lane)
    const int i0 = w * 8;              // 8 token rows per warp
    const int li = lane >> 3, lj = lane & 7;

    float s[2][8];
#pragma unroll
    for (int t = 0; t < 2; t++)
#pragma unroll
        for (int m = 0; m < 8; m++) s[t][m] = 0.0f;

#pragma unroll 4
    for (int c = 0; c < 64; c++) {
        float qv[2], kv[8];
#pragma unroll
        for (int t = 0; t < 2; t++) qv[t] = QS[(i0 + li + 4 * t) * 65 + c];
#pragma unroll
        for (int m = 0; m < 8; m++) kv[m] = KS[(lj + 8 * m) * 65 + c];
#pragma unroll
        for (int t = 0; t < 2; t++)
#pragma unroll
            for (int m = 0; m < 8; m++) s[t][m] += qv[t] * kv[m];
    }

#pragma unroll
    for (int t = 0; t < 2; t++) {
        const int row = i0 + li + 4 * t;
        float mt = -3.0e38f;
#pragma unroll
        for (int m = 0; m < 8; m++) {
            int col = lj + 8 * m;
            float v = s[t][m] * 0.125f;
            v = (col <= row) ? v : -3.0e38f;
            s[t][m] = v;
            mt = fmaxf(mt, v);
        }
        mt = fmaxf(mt, __shfl_xor_sync(0xffffffffu, mt, 1));
        mt = fmaxf(mt, __shfl_xor_sync(0xffffffffu, mt, 2));
        mt = fmaxf(mt, __shfl_xor_sync(0xffffffffu, mt, 4));
        float sum = 0.0f;
#pragma unroll
        for (int m = 0; m < 8; m++) {
            float e = __expf(s[t][m] - mt);
            s[t][m] = e;
            sum += e;
        }
        sum += __shfl_xor_sync(0xffffffffu, sum, 1);
        sum += __shfl_xor_sync(0xffffffffu, sum, 2);
        sum += __shfl_xor_sync(0xffffffffu, sum, 4);
        float inv = 1.0f / sum;
#pragma unroll
        for (int m = 0; m < 8; m++)
            PS[row * 65 + lj + 8 * m] = s[t][m] * inv;
    }
    __syncthreads();

    // -------- out = P @ v
    float o[2][8];
#pragma unroll
    for (int t = 0; t < 2; t++)
#pragma unroll
        for (int m = 0; m < 8; m++) o[t][m] = 0.0f;

#pragma unroll 4
    for (int cs = 0; cs < 64; cs++) {
        float pv[2], vv[8];
#pragma unroll
        for (int t = 0; t < 2; t++) pv[t] = PS[(i0 + li + 4 * t) * 65 + cs];
#pragma unroll
        for (int m = 0; m < 8; m++) vv[m] = VS[cs * 65 + lj + 8 * m];
#pragma unroll
        for (int t = 0; t < 2; t++)
#pragma unroll
            for (int m = 0; m < 8; m++) o[t][m] += pv[t] * vv[m];
    }
    __syncthreads();  // PS reads done -> reuse as staging

    float* OS = PS;  // [64][64]
#pragma unroll
    for (int t = 0; t < 2; t++)
#pragma unroll
        for (int m = 0; m < 8; m++)
            OS[(i0 + li + 4 * t) * 64 + lj + 8 * m] = o[t][m];
    __syncthreads();

    float4* og = (float4*)(out + (size_t)blockIdx.x * 4096);
    const float4* os4 = (const float4*)OS;
#pragma unroll
    for (int i = tid; i < 1024; i += NT) og[i] = os4[i];
}

extern "C" void kernel_launch(void* const* d_in, const int* in_sizes, int n_in,
                              void* d_out, int out_size) {
    const float* x  = (const float*)d_in[0];
    const float* Wk = (const float*)d_in[1];
    const float* Wq = (const float*)d_in[2];
    const float* Wv = (const float*)d_in[3];
    float* out = (float*)d_out;

    cudaFuncSetAttribute(head_main, cudaFuncAttributeMaxDynamicSharedMemorySize, SMEM_BYTES);

    prep_weights<<<(CCH * NK + 255) / 256, 256>>>(Wk, Wq, Wv);
    head_main<<<2048, NT, SMEM_BYTES>>>(x, out);
}

// round 8
// speedup vs baseline: 1.4889x; 1.3368x over previous
#include <cuda_runtime.h>
#include <cuda_fp16.h>
#include <cstdint>

#define CCH 768
#define NK  192
#define NCHUNK 12
#define NT 256

// smem (bytes), per CTA (2 CTAs/SM):
//  projection: XH fp16 [64][72] @0 (9216); W bufs @9216, per buf 25600 -> end 60416
//  attention overlay: KS/QS/VS/PS fp32, each 64*65*4 = 16640 -> 66560 total
#define WOFF(b) (9216 + (b) * 25600)
#define SMEM_BYTES 66560

__device__ __align__(16) __half g_W[CCH * NK];

__global__ void prep_weights(const float* __restrict__ Wk,
                             const float* __restrict__ Wq,
                             const float* __restrict__ Wv) {
    int i = blockIdx.x * blockDim.x + threadIdx.x;
    if (i >= CCH * NK) return;
    int c = i / NK, n = i % NK;
    const float* W = (n < 64) ? Wk : (n < 128) ? Wq : Wv;
    g_W[i] = __float2half_rn(W[c * 64 + (n & 63)]);
}

__device__ __forceinline__ uint32_t sptr(const void* p) {
    return (uint32_t)__cvta_generic_to_shared(p);
}
__device__ __forceinline__ void ldsm_x4(uint32_t* r, uint32_t addr) {
    asm volatile("ldmatrix.sync.aligned.m8n8.x4.shared.b16 {%0,%1,%2,%3}, [%4];"
                 : "=r"(r[0]), "=r"(r[1]), "=r"(r[2]), "=r"(r[3]) : "r"(addr));
}
__device__ __forceinline__ void ldsm_x4t(uint32_t* r, uint32_t addr) {
    asm volatile("ldmatrix.sync.aligned.m8n8.x4.trans.shared.b16 {%0,%1,%2,%3}, [%4];"
                 : "=r"(r[0]), "=r"(r[1]), "=r"(r[2]), "=r"(r[3]) : "r"(addr));
}
__device__ __forceinline__ void mma16816(float* c, const uint32_t* a, const uint32_t* b) {
    asm volatile("mma.sync.aligned.m16n8k16.row.col.f32.f16.f16.f32 "
                 "{%0,%1,%2,%3}, {%4,%5,%6,%7}, {%8,%9}, {%0,%1,%2,%3};"
                 : "+f"(c[0]), "+f"(c[1]), "+f"(c[2]), "+f"(c[3])
                 : "r"(a[0]), "r"(a[1]), "r"(a[2]), "r"(a[3]), "r"(b[0]), "r"(b[1]));
}
__device__ __forceinline__ void cpasync16(uint32_t d, const void* s) {
    asm volatile("cp.async.cg.shared.global [%0], [%1], 16;" :: "r"(d), "l"(s));
}

extern "C" __global__ void __launch_bounds__(NT, 2)
head_main(const float* __restrict__ x, float* __restrict__ out) {
    extern __shared__ char smem[];
    __half* XH = (__half*)smem;

    const int tid = threadIdx.x;
    const int w = tid >> 5;
    const int lane = tid & 31;

    const float* xb = x + (size_t)blockIdx.x * 64 * CCH;

    // -------- prefetch x chunk 0: 64 rows x 16 float4; 4 float4/thread
    float4 xr[4];
#pragma unroll
    for (int i = 0; i < 4; i++) {
        int idx = i * NT + tid;
        xr[i] = *(const float4*)(xb + (idx >> 4) * CCH + (idx & 15) * 4);
    }

    // -------- issue W chunk 0 -> buf 0
#pragma unroll
    for (int j = 0; j < 6; j++) {
        int idx = j * NT + tid;                 // 1536: 64 k-rows x 24 16B-segs
        int row = idx / 24, c16 = (idx % 24) * 8;
        cpasync16(sptr(smem + WOFF(0)) + (uint32_t)(row * 400 + c16 * 2),
                  g_W + row * NK + c16);
    }
    asm volatile("cp.async.commit_group;" ::: "memory");

    // warp grid 2x4: M32 x N48 per warp
    const int mwarp = w & 1;                    // M tile of 32 rows
    const int nwarp = w >> 1;                   // N tile of 48 cols

    float acc[12][4];                           // [mt*6 + jn][4], mt<2, jn<6
#pragma unroll
    for (int jt = 0; jt < 12; jt++)
#pragma unroll
        for (int r = 0; r < 4; r++) acc[jt][r] = 0.0f;

    const int a_base = (mwarp * 32 + (lane & 15)) * 72 + (lane >> 4) * 8;  // halves
    const int b_base = nwarp * 48 + (lane >> 4) * 8;                       // col part
    const int b_row = lane & 15;

#pragma unroll 1
    for (int kc = 0; kc < NCHUNK; kc++) {
        const int buf = kc & 1;
        __syncthreads();  // prev chunk's MMA reads of XH and W[buf^1] complete

        if (kc + 1 < NCHUNK) {
            const size_t gk = (size_t)(kc + 1) * 64 * NK;
#pragma unroll
            for (int j = 0; j < 6; j++) {
                int idx = j * NT + tid;
                int row = idx / 24, c16 = (idx % 24) * 8;
                cpasync16(sptr(smem + WOFF(buf ^ 1)) + (uint32_t)(row * 400 + c16 * 2),
                          g_W + gk + row * NK + c16);
            }
            asm volatile("cp.async.commit_group;" ::: "memory");
        }

        // x regs -> XH fp16 (single rounding)
#pragma unroll
        for (int i = 0; i < 4; i++) {
            int idx = i * NT + tid;
            int r = idx >> 4, s = idx & 15;
            float4 v = xr[i];
            __half2 h01 = __floats2half2_rn(v.x, v.y);
            __half2 h23 = __floats2half2_rn(v.z, v.w);
            uint2 pkt;
            pkt.x = *(uint32_t*)&h01;
            pkt.y = *(uint32_t*)&h23;
            *(uint2*)((char*)XH + (uint32_t)(r * 144 + s * 8)) = pkt;
        }

        if (kc + 1 < NCHUNK) asm volatile("cp.async.wait_group 1;" ::: "memory");
        else                 asm volatile("cp.async.wait_group 0;" ::: "memory");
        __syncthreads();  // XH + W[buf] visible to all

        // prefetch next x chunk
        if (kc + 1 < NCHUNK) {
#pragma unroll
            for (int i = 0; i < 4; i++) {
                int idx = i * NT + tid;
                xr[i] = *(const float4*)(xb + (idx >> 4) * CCH + (kc + 1) * 64 + (idx & 15) * 4);
            }
        }

        const __half* WHs = (const __half*)(smem + WOFF(buf));

#pragma unroll
        for (int ks = 0; ks < 4; ks++) {
            uint32_t ah0[4], ah1[4];
            ldsm_x4(ah0, sptr(XH + a_base + ks * 16));
            ldsm_x4(ah1, sptr(XH + a_base + 16 * 72 + ks * 16));
            const int br = (ks * 16 + b_row) * 200 + b_base;
#pragma unroll
            for (int j = 0; j < 3; j++) {
                uint32_t bh[4];
                ldsm_x4t(bh, sptr(WHs + br + j * 16));
                mma16816(acc[0 * 6 + 2 * j],     ah0, bh);
                mma16816(acc[0 * 6 + 2 * j + 1], ah0, bh + 2);
                mma16816(acc[1 * 6 + 2 * j],     ah1, bh);
                mma16816(acc[1 * 6 + 2 * j + 1], ah1, bh + 2);
            }
        }
    }
    __syncthreads();  // projection done; smem repurposed

    // -------- fragments -> KS/QS/VS (fp32, row pad 65)
    float* KS = (float*)smem;
    float* QS = KS + 4160;   // 64*65
    float* VS = QS + 4160;
    float* PS = VS + 4160;
    {
        const int c2 = (lane & 3) * 2;
#pragma unroll
        for (int mt = 0; mt < 2; mt++) {
            const int tr = mwarp * 32 + mt * 16 + (lane >> 2);
#pragma unroll
            for (int jn = 0; jn < 6; jn++) {
                int col = nwarp * 48 + jn * 8 + c2;
                float* dst = (col < 64) ? (KS + col) : (col < 128) ? (QS + col - 64) : (VS + col - 128);
                float* p0 = dst + tr * 65;
                const float* a = acc[mt * 6 + jn];
                p0[0] = a[0];
                p0[1] = a[1];
                p0[8 * 65] = a[2];
                p0[8 * 65 + 1] = a[3];
            }
        }
    }
    __syncthreads();

    // -------- S = q k^T * 0.125, causal softmax (fp32, 2x8 microtile per lane)
    const int i0 = w * 8;              // 8 token rows per warp
    const int li = lane >> 3, lj = lane & 7;

    float s[2][8];
#pragma unroll
    for (int t = 0; t < 2; t++)
#pragma unroll
        for (int m = 0; m < 8; m++) s[t][m] = 0.0f;

#pragma unroll 4
    for (int c = 0; c < 64; c++) {
        float qv[2], kv[8];
#pragma unroll
        for (int t = 0; t < 2; t++) qv[t] = QS[(i0 + li + 4 * t) * 65 + c];
#pragma unroll
        for (int m = 0; m < 8; m++) kv[m] = KS[(lj + 8 * m) * 65 + c];
#pragma unroll
        for (int t = 0; t < 2; t++)
#pragma unroll
            for (int m = 0; m < 8; m++) s[t][m] += qv[t] * kv[m];
    }

#pragma unroll
    for (int t = 0; t < 2; t++) {
        const int row = i0 + li + 4 * t;
        float mt = -3.0e38f;
#pragma unroll
        for (int m = 0; m < 8; m++) {
            int col = lj + 8 * m;
            float v = s[t][m] * 0.125f;
            v = (col <= row) ? v : -3.0e38f;
            s[t][m] = v;
            mt = fmaxf(mt, v);
        }
        mt = fmaxf(mt, __shfl_xor_sync(0xffffffffu, mt, 1));
        mt = fmaxf(mt, __shfl_xor_sync(0xffffffffu, mt, 2));
        mt = fmaxf(mt, __shfl_xor_sync(0xffffffffu, mt, 4));
        float sum = 0.0f;
#pragma unroll
        for (int m = 0; m < 8; m++) {
            float e = __expf(s[t][m] - mt);
            s[t][m] = e;
            sum += e;
        }
        sum += __shfl_xor_sync(0xffffffffu, sum, 1);
        sum += __shfl_xor_sync(0xffffffffu, sum, 2);
        sum += __shfl_xor_sync(0xffffffffu, sum, 4);
        float inv = 1.0f / sum;
#pragma unroll
        for (int m = 0; m < 8; m++)
            PS[row * 65 + lj + 8 * m] = s[t][m] * inv;
    }
    __syncthreads();

    // -------- out = P @ v
    float o[2][8];
#pragma unroll
    for (int t = 0; t < 2; t++)
#pragma unroll
        for (int m = 0; m < 8; m++) o[t][m] = 0.0f;

#pragma unroll 4
    for (int cs = 0; cs < 64; cs++) {
        float pv[2], vv[8];
#pragma unroll
        for (int t = 0; t < 2; t++) pv[t] = PS[(i0 + li + 4 * t) * 65 + cs];
#pragma unroll
        for (int m = 0; m < 8; m++) vv[m] = VS[cs * 65 + lj + 8 * m];
#pragma unroll
        for (int t = 0; t < 2; t++)
#pragma unroll
            for (int m = 0; m < 8; m++) o[t][m] += pv[t] * vv[m];
    }
    __syncthreads();  // PS reads done -> reuse as staging

    float* OS = PS;  // [64][64]
#pragma unroll
    for (int t = 0; t < 2; t++)
#pragma unroll
        for (int m = 0; m < 8; m++)
            OS[(i0 + li + 4 * t) * 64 + lj + 8 * m] = o[t][m];
    __syncthreads();

    float4* og = (float4*)(out + (size_t)blockIdx.x * 4096);
    const float4* os4 = (const float4*)OS;
#pragma unroll
    for (int i = tid; i < 1024; i += NT) og[i] = os4[i];
}

extern "C" void kernel_launch(void* const* d_in, const int* in_sizes, int n_in,
                              void* d_out, int out_size) {
    const float* x  = (const float*)d_in[0];
    const float* Wk = (const float*)d_in[1];
    const float* Wq = (const float*)d_in[2];
    const float* Wv = (const float*)d_in[3];
    float* out = (float*)d_out;

    cudaFuncSetAttribute(head_main, cudaFuncAttributeMaxDynamicSharedMemorySize, SMEM_BYTES);

    prep_weights<<<(CCH * NK + 255) / 256, 256>>>(Wk, Wq, Wv);
    head_main<<<2048, NT, SMEM_BYTES>>>(x, out);
}

// round 9
// speedup vs baseline: 2.2356x; 1.5015x over previous
#include <cuda_runtime.h>
#include <cuda_fp16.h>
#include <cstdint>

#define CCH 768
#define NK  192
#define NCHUNK 12
#define NT 256

// smem (bytes), per CTA (2 CTAs/SM):
//  projection: XH fp16 [64][72] @0 (9216); W bufs @9216, per buf 25600 -> end 60416
//  attention overlay: KH/QH/VH fp16 [64][72] each 9216 -> 27648 total
#define WOFF(b) (9216 + (b) * 25600)
#define SMEM_BYTES 66560

__device__ __align__(16) __half g_W[CCH * NK];

__global__ void prep_weights(const float* __restrict__ Wk,
                             const float* __restrict__ Wq,
                             const float* __restrict__ Wv) {
    int i = blockIdx.x * blockDim.x + threadIdx.x;
    if (i >= CCH * NK) return;
    int c = i / NK, n = i % NK;
    const float* W = (n < 64) ? Wk : (n < 128) ? Wq : Wv;
    g_W[i] = __float2half_rn(W[c * 64 + (n & 63)]);
}

__device__ __forceinline__ uint32_t sptr(const void* p) {
    return (uint32_t)__cvta_generic_to_shared(p);
}
__device__ __forceinline__ void ldsm_x4(uint32_t* r, uint32_t addr) {
    asm volatile("ldmatrix.sync.aligned.m8n8.x4.shared.b16 {%0,%1,%2,%3}, [%4];"
                 : "=r"(r[0]), "=r"(r[1]), "=r"(r[2]), "=r"(r[3]) : "r"(addr));
}
__device__ __forceinline__ void ldsm_x4t(uint32_t* r, uint32_t addr) {
    asm volatile("ldmatrix.sync.aligned.m8n8.x4.trans.shared.b16 {%0,%1,%2,%3}, [%4];"
                 : "=r"(r[0]), "=r"(r[1]), "=r"(r[2]), "=r"(r[3]) : "r"(addr));
}
__device__ __forceinline__ void mma16816(float* c, const uint32_t* a, const uint32_t* b) {
    asm volatile("mma.sync.aligned.m16n8k16.row.col.f32.f16.f16.f32 "
                 "{%0,%1,%2,%3}, {%4,%5,%6,%7}, {%8,%9}, {%0,%1,%2,%3};"
                 : "+f"(c[0]), "+f"(c[1]), "+f"(c[2]), "+f"(c[3])
                 : "r"(a[0]), "r"(a[1]), "r"(a[2]), "r"(a[3]), "r"(b[0]), "r"(b[1]));
}
__device__ __forceinline__ void cpasync16(uint32_t d, const void* s) {
    asm volatile("cp.async.cg.shared.global [%0], [%1], 16;" :: "r"(d), "l"(s));
}
__device__ __forceinline__ uint32_t packh2(float a, float b) {
    __half2 h = __floats2half2_rn(a, b);
    return *(uint32_t*)&h;
}

extern "C" __global__ void __launch_bounds__(NT, 2)
head_main(const float* __restrict__ x, float* __restrict__ out) {
    extern __shared__ char smem[];
    __half* XH = (__half*)smem;

    const int tid = threadIdx.x;
    const int w = tid >> 5;
    const int lane = tid & 31;

    const float* xb = x + (size_t)blockIdx.x * 64 * CCH;

    // -------- prefetch x chunk 0
    float4 xr[4];
#pragma unroll
    for (int i = 0; i < 4; i++) {
        int idx = i * NT + tid;
        xr[i] = *(const float4*)(xb + (idx >> 4) * CCH + (idx & 15) * 4);
    }

    // -------- issue W chunk 0 -> buf 0
#pragma unroll
    for (int j = 0; j < 6; j++) {
        int idx = j * NT + tid;
        int row = idx / 24, c16 = (idx % 24) * 8;
        cpasync16(sptr(smem + WOFF(0)) + (uint32_t)(row * 400 + c16 * 2),
                  g_W + row * NK + c16);
    }
    asm volatile("cp.async.commit_group;" ::: "memory");

    // warp grid 2x4: M32 x N48 per warp
    const int mwarp = w & 1;
    const int nwarp = w >> 1;

    float acc[12][4];
#pragma unroll
    for (int jt = 0; jt < 12; jt++)
#pragma unroll
        for (int r = 0; r < 4; r++) acc[jt][r] = 0.0f;

    const int a_base = (mwarp * 32 + (lane & 15)) * 72 + (lane >> 4) * 8;
    const int b_base = nwarp * 48 + (lane >> 4) * 8;
    const int b_row = lane & 15;

#pragma unroll 1
    for (int kc = 0; kc < NCHUNK; kc++) {
        const int buf = kc & 1;
        __syncthreads();

        if (kc + 1 < NCHUNK) {
            const size_t gk = (size_t)(kc + 1) * 64 * NK;
#pragma unroll
            for (int j = 0; j < 6; j++) {
                int idx = j * NT + tid;
                int row = idx / 24, c16 = (idx % 24) * 8;
                cpasync16(sptr(smem + WOFF(buf ^ 1)) + (uint32_t)(row * 400 + c16 * 2),
                          g_W + gk + row * NK + c16);
            }
            asm volatile("cp.async.commit_group;" ::: "memory");
        }

        // x regs -> XH fp16
#pragma unroll
        for (int i = 0; i < 4; i++) {
            int idx = i * NT + tid;
            int r = idx >> 4, s = idx & 15;
            float4 v = xr[i];
            uint2 pkt;
            pkt.x = packh2(v.x, v.y);
            pkt.y = packh2(v.z, v.w);
            *(uint2*)((char*)XH + (uint32_t)(r * 144 + s * 8)) = pkt;
        }

        if (kc + 1 < NCHUNK) asm volatile("cp.async.wait_group 1;" ::: "memory");
        else                 asm volatile("cp.async.wait_group 0;" ::: "memory");
        __syncthreads();

        if (kc + 1 < NCHUNK) {
#pragma unroll
            for (int i = 0; i < 4; i++) {
                int idx = i * NT + tid;
                xr[i] = *(const float4*)(xb + (idx >> 4) * CCH + (kc + 1) * 64 + (idx & 15) * 4);
            }
        }

        const __half* WHs = (const __half*)(smem + WOFF(buf));

#pragma unroll
        for (int ks = 0; ks < 4; ks++) {
            uint32_t ah0[4], ah1[4];
            ldsm_x4(ah0, sptr(XH + a_base + ks * 16));
            ldsm_x4(ah1, sptr(XH + a_base + 16 * 72 + ks * 16));
            const int br = (ks * 16 + b_row) * 200 + b_base;
#pragma unroll
            for (int j = 0; j < 3; j++) {
                uint32_t bh[4];
                ldsm_x4t(bh, sptr(WHs + br + j * 16));
                mma16816(acc[0 * 6 + 2 * j],     ah0, bh);
                mma16816(acc[0 * 6 + 2 * j + 1], ah0, bh + 2);
                mma16816(acc[1 * 6 + 2 * j],     ah1, bh);
                mma16816(acc[1 * 6 + 2 * j + 1], ah1, bh + 2);
            }
        }
    }
    __syncthreads();  // projection done; smem repurposed

    // -------- fragments -> KH/QH/VH (fp16, [64][72])
    __half* KH = (__half*)smem;
    __half* QH = KH + 4608;
    __half* VH = QH + 4608;
    {
        const int c2 = (lane & 3) * 2;
#pragma unroll
        for (int mt = 0; mt < 2; mt++) {
            const int tr = mwarp * 32 + mt * 16 + (lane >> 2);
#pragma unroll
            for (int jn = 0; jn < 6; jn++) {
                int col = nwarp * 48 + jn * 8 + c2;
                __half* dst = (col < 64) ? (KH + col) : (col < 128) ? (QH + col - 64) : (VH + col - 128);
                const float* a = acc[mt * 6 + jn];
                *(uint32_t*)(dst + tr * 72)       = packh2(a[0], a[1]);
                *(uint32_t*)(dst + (tr + 8) * 72) = packh2(a[2], a[3]);
            }
        }
    }
    __syncthreads();

    // -------- attention via MMA: warps 0-3, strip of 16 rows each
    if (w < 4) {
        const int g = lane >> 2;          // row within 8-row group
        const int t2 = (lane & 3) * 2;    // col pair within n-tile
        const int row0 = w * 16 + g;
        const int row1 = row0 + 8;

        // S = Q @ K^T : sc[nj] covers cols 8nj..8nj+7
        float sc[8][4];
#pragma unroll
        for (int nj = 0; nj < 8; nj++)
#pragma unroll
            for (int r = 0; r < 4; r++) sc[nj][r] = 0.0f;

        const int a_q = (w * 16 + (lane & 15)) * 72 + (lane >> 4) * 8;
        const int kb_row = (lane & 7) + ((lane >> 4) << 3);   // token row for B tiles
        const int kb_off = ((lane >> 3) & 1) * 8;             // k halves offset
#pragma unroll
        for (int kk = 0; kk < 4; kk++) {
            uint32_t aq[4];
            ldsm_x4(aq, sptr(QH + a_q + kk * 16));
#pragma unroll
            for (int jn = 0; jn < 4; jn++) {
                uint32_t bk[4];
                ldsm_x4(bk, sptr(KH + (jn * 16 + kb_row) * 72 + kk * 16 + kb_off));
                mma16816(sc[2 * jn],     aq, bk);
                mma16816(sc[2 * jn + 1], aq, bk + 2);
            }
        }

        // scale + causal mask + softmax (rows row0 and row1)
        float m0 = -3.0e38f, m1 = -3.0e38f;
#pragma unroll
        for (int nj = 0; nj < 8; nj++) {
#pragma unroll
            for (int e = 0; e < 2; e++) {
                int col = 8 * nj + t2 + e;
                float v0 = sc[nj][e] * 0.125f;
                float v1 = sc[nj][2 + e] * 0.125f;
                v0 = (col <= row0) ? v0 : -3.0e38f;
                v1 = (col <= row1) ? v1 : -3.0e38f;
                sc[nj][e] = v0;
                sc[nj][2 + e] = v1;
                m0 = fmaxf(m0, v0);
                m1 = fmaxf(m1, v1);
            }
        }
        m0 = fmaxf(m0, __shfl_xor_sync(0xffffffffu, m0, 1));
        m0 = fmaxf(m0, __shfl_xor_sync(0xffffffffu, m0, 2));
        m1 = fmaxf(m1, __shfl_xor_sync(0xffffffffu, m1, 1));
        m1 = fmaxf(m1, __shfl_xor_sync(0xffffffffu, m1, 2));
        float s0 = 0.0f, s1 = 0.0f;
#pragma unroll
        for (int nj = 0; nj < 8; nj++) {
#pragma unroll
            for (int e = 0; e < 2; e++) {
                float e0 = __expf(sc[nj][e] - m0);
                float e1 = __expf(sc[nj][2 + e] - m1);
                sc[nj][e] = e0;
                sc[nj][2 + e] = e1;
                s0 += e0;
                s1 += e1;
            }
        }
        s0 += __shfl_xor_sync(0xffffffffu, s0, 1);
        s0 += __shfl_xor_sync(0xffffffffu, s0, 2);
        s1 += __shfl_xor_sync(0xffffffffu, s1, 1);
        s1 += __shfl_xor_sync(0xffffffffu, s1, 2);
        const float i0v = 1.0f / s0, i1v = 1.0f / s1;
#pragma unroll
        for (int nj = 0; nj < 8; nj++) {
            sc[nj][0] *= i0v; sc[nj][1] *= i0v;
            sc[nj][2] *= i1v; sc[nj][3] *= i1v;
        }

        // out = P @ V : P register->register into A fragments; B = V via ldsm_x4t
        float oc[8][4];
#pragma unroll
        for (int nj = 0; nj < 8; nj++)
#pragma unroll
            for (int r = 0; r < 4; r++) oc[nj][r] = 0.0f;

        const int v_row = lane & 15;
        const int v_off = (lane >> 4) * 8;
#pragma unroll 1
        for (int kk = 0; kk <= w; kk++) {   // tokens > 16w+15 have P == 0 exactly
            uint32_t pa[4];
            pa[0] = packh2(sc[2 * kk][0],     sc[2 * kk][1]);
            pa[1] = packh2(sc[2 * kk][2],     sc[2 * kk][3]);
            pa[2] = packh2(sc[2 * kk + 1][0], sc[2 * kk + 1][1]);
            pa[3] = packh2(sc[2 * kk + 1][2], sc[2 * kk + 1][3]);
            const __half* vb = VH + (16 * kk + v_row) * 72 + v_off;
#pragma unroll
            for (int jn = 0; jn < 4; jn++) {
                uint32_t bv[4];
                ldsm_x4t(bv, sptr(vb + jn * 16));
                mma16816(oc[2 * jn],     pa, bv);
                mma16816(oc[2 * jn + 1], pa, bv + 2);
            }
        }

        // store directly to gmem (float2 per c-pair)
        float* ob = out + (size_t)blockIdx.x * 4096;
#pragma unroll
        for (int nj = 0; nj < 8; nj++) {
            int col = 8 * nj + t2;
            float2 v0 = make_float2(oc[nj][0], oc[nj][1]);
            float2 v1 = make_float2(oc[nj][2], oc[nj][3]);
            *(float2*)(ob + row0 * 64 + col) = v0;
            *(float2*)(ob + row1 * 64 + col) = v1;
        }
    }
}

extern "C" void kernel_launch(void* const* d_in, const int* in_sizes, int n_in,
                              void* d_out, int out_size) {
    const float* x  = (const float*)d_in[0];
    const float* Wk = (const float*)d_in[1];
    const float* Wq = (const float*)d_in[2];
    const float* Wv = (const float*)d_in[3];
    float* out = (float*)d_out;

    cudaFuncSetAttribute(head_main, cudaFuncAttributeMaxDynamicSharedMemorySize, SMEM_BYTES);

    prep_weights<<<(CCH * NK + 255) / 256, 256>>>(Wk, Wq, Wv);
    head_main<<<2048, NT, SMEM_BYTES>>>(x, out);
}